// round 14
// baseline (speedup 1.0000x reference)
#include <cuda_runtime.h>
#include <cuda_bf16.h>
#include <cstdint>
#include <cstdio>

#define NMAX 50000

// scratch (allocation-free: __device__ globals)
__device__ __align__(16) float g_Q[NMAX * 192];      // [h@W1a | h@W1b | h@Wn1a]
__device__ __align__(16) float g_totf[NMAX * 4];     // {fx, fy, fz, deg}
__device__ __align__(16) float g_totmsg[NMAX * 64];

typedef unsigned long long u64t;

__device__ __forceinline__ float silu_f(float v) {
    return __fdividef(v, 1.0f + __expf(-v));
}
// 1-MUFU silu via tanh.approx: silu(x) = 0.5x*(1+tanh(0.5x))
__device__ __forceinline__ float silu_t(float v) {
    float hx = 0.5f * v, t;
    asm("tanh.approx.f32 %0,%1;" : "=f"(t) : "f"(hx));
    return fmaf(hx, t, hx);
}
__device__ __forceinline__ u64t pk2(float lo, float hi) {
    u64t r; asm("mov.b64 %0,{%1,%2};" : "=l"(r) : "f"(lo), "f"(hi)); return r;
}
__device__ __forceinline__ void unpk2(u64t v, float& a, float& b) {
    asm("mov.b64 {%0,%1},%2;" : "=f"(a), "=f"(b) : "l"(v));
}
__device__ __forceinline__ u64t fma2(u64t a, u64t b, u64t c) {
    u64t d; asm("fma.rn.f32x2 %0,%1,%2,%3;" : "=l"(d) : "l"(a), "l"(b), "l"(c)); return d;
}
__device__ __forceinline__ u64t add2(u64t a, u64t b) {
    u64t d; asm("add.rn.f32x2 %0,%1,%2;" : "=l"(d) : "l"(a), "l"(b)); return d;
}
__device__ __forceinline__ void red4(float* p, float a, float b, float c, float d) {
    asm volatile("red.global.add.v4.f32 [%0], {%1,%2,%3,%4};"
                 :: "l"(p), "f"(a), "f"(b), "f"(c), "f"(d) : "memory");
}
__device__ __forceinline__ void red2(float* p, float a, float b) {
    asm volatile("red.global.add.v2.f32 [%0], {%1,%2};"
                 :: "l"(p), "f"(a), "f"(b) : "memory");
}
__device__ __forceinline__ void bf_split(float v, __nv_bfloat16& h, __nv_bfloat16& l) {
    h = __float2bfloat16(v);
    l = __float2bfloat16(v - __bfloat162float(h));
}
__device__ __forceinline__ uint32_t pkbf(__nv_bfloat16 a, __nv_bfloat16 b) {
    __nv_bfloat162 t; t.x = a; t.y = b;
    return *reinterpret_cast<uint32_t*>(&t);
}
__device__ __forceinline__ uint32_t s2u(const void* p) {
    uint32_t a;
    asm("{ .reg .u64 t; cvta.to.shared.u64 t, %1; cvt.u32.u64 %0, t; }" : "=r"(a) : "l"(p));
    return a;
}
__device__ __forceinline__ void mma16816(float* d, const uint32_t* a, uint32_t b0, uint32_t b1) {
    asm volatile(
        "mma.sync.aligned.m16n8k16.row.col.f32.bf16.bf16.f32 "
        "{%0,%1,%2,%3},{%4,%5,%6,%7},{%8,%9},{%0,%1,%2,%3};"
        : "+f"(d[0]), "+f"(d[1]), "+f"(d[2]), "+f"(d[3])
        : "r"(a[0]), "r"(a[1]), "r"(a[2]), "r"(a[3]), "r"(b0), "r"(b1));
}
__device__ __forceinline__ void ldsm4(uint32_t* r, uint32_t addr) {
    asm volatile("ldmatrix.sync.aligned.m8n8.x4.shared.b16 {%0,%1,%2,%3},[%4];"
        : "=r"(r[0]), "=r"(r[1]), "=r"(r[2]), "=r"(r[3]) : "r"(addr));
}
__device__ __forceinline__ void ldsm4t(uint32_t* r, uint32_t addr) {
    asm volatile("ldmatrix.sync.aligned.m8n8.x4.trans.shared.b16 {%0,%1,%2,%3},[%4];"
        : "=r"(r[0]), "=r"(r[1]), "=r"(r[2]), "=r"(r[3]) : "r"(addr));
}

// ------------------------------------------------- per-node linear precompute
// g_Q[n][0:192] = h[n] @ [W1a | W1b | Wn1a], split-bf16 HMMA GEMM.
// Persistent-ish: grid 304, weights staged ONCE per CTA, loop over 128-node tiles.
#define QA_STRIDE 272
#define QW_STRIDE 400
#define QSM_A 0                 // 128 * 272 = 34816
#define QSM_W 34816             // 128 * 400 = 51200 ([Whi(64 k-rows); Wlo(64)] x 192 cols)
#define QSM_BYTES 86016

__global__ __launch_bounds__(256) void precompQ(
    const float* __restrict__ h, const float* __restrict__ w1e,
    const float* __restrict__ wn1, int N)
{
    extern __shared__ __align__(1024) char qsm[];
    const uint32_t sb = s2u(qsm);
    const int tid = threadIdx.x;
    const int wid = tid >> 5, lane = tid & 31;

    // zero accumulators (independent of the rest)
    {
        int gi = blockIdx.x * blockDim.x + tid;
        int gs = gridDim.x * blockDim.x;
        float4 z = make_float4(0.f, 0.f, 0.f, 0.f);
        float4* tf = reinterpret_cast<float4*>(g_totf);
        float4* tm = reinterpret_cast<float4*>(g_totmsg);
        for (int k = gi; k < N; k += gs) tf[k] = z;
        for (int k = gi; k < N * 16; k += gs) tm[k] = z;
    }

    // stage + split weights ONCE: k (0..63) x col-pair cp (0..95), packed u32 stores
    for (int i = tid; i < 64 * 96; i += 256) {
        int k = i / 96, cp = i - k * 96;
        int c0 = cp * 2, c1 = c0 + 1;   // same 64-col region (c0 even)
        float v0 = (c0 < 64) ? w1e[(1 + k) * 64 + c0]
                 : (c0 < 128) ? w1e[(65 + k) * 64 + (c0 - 64)]
                              : wn1[k * 64 + (c0 - 128)];
        float v1 = (c1 < 64) ? w1e[(1 + k) * 64 + c1]
                 : (c1 < 128) ? w1e[(65 + k) * 64 + (c1 - 64)]
                              : wn1[k * 64 + (c1 - 128)];
        __nv_bfloat16 h0, l0, h1, l1;
        bf_split(v0, h0, l0); bf_split(v1, h1, l1);
        *reinterpret_cast<uint32_t*>(qsm + QSM_W + k * QW_STRIDE + c0 * 2) = pkbf(h0, h1);
        *reinterpret_cast<uint32_t*>(qsm + QSM_W + (64 + k) * QW_STRIDE + c0 * 2) = pkbf(l0, l1);
    }

    // static per-thread ldmatrix addresses
    const uint32_t a_ld = sb + QSM_A + (uint32_t)(wid * 16 + (lane & 15)) * QA_STRIDE
                        + ((lane >> 4) << 4);
    const int g = lane >> 3, rr = lane & 7;
    const uint32_t b_ld = sb + QSM_W + (uint32_t)((g & 1) * 8 + rr) * QW_STRIDE + (g >> 1) * 16;
    const int rsub = lane >> 2, cpair = (lane & 3) * 2;

    const int ntile = (N + 127) >> 7;
    for (int tile = blockIdx.x; tile < ntile; tile += gridDim.x) {
        const int n0 = tile << 7;
        __syncthreads();   // previous-tile GEMM reads done before A rewrite (also orders W staging)
        // stage h tile [128 x 64] -> A [hi|lo] bf16
        {
            const int le = tid >> 1, sub = tid & 1, j0 = sub << 5;
            const int n = n0 + le;
            char* arow = qsm + QSM_A + le * QA_STRIDE;
            if (n < N) {
                const float4* hp = reinterpret_cast<const float4*>(h + (size_t)n * 64 + j0);
                #pragma unroll
                for (int v = 0; v < 8; v++) {
                    float4 hv = hp[v];
                    __nv_bfloat16 ah, al, bh, bl, ch, cl, dh, dl;
                    bf_split(hv.x, ah, al); bf_split(hv.y, bh, bl);
                    bf_split(hv.z, ch, cl); bf_split(hv.w, dh, dl);
                    *reinterpret_cast<uint32_t*>(arow + (j0 + 4 * v) * 2)       = pkbf(ah, bh);
                    *reinterpret_cast<uint32_t*>(arow + (j0 + 4 * v + 2) * 2)   = pkbf(ch, dh);
                    *reinterpret_cast<uint32_t*>(arow + (64 + j0 + 4 * v) * 2)     = pkbf(al, bl);
                    *reinterpret_cast<uint32_t*>(arow + (64 + j0 + 4 * v + 2) * 2) = pkbf(cl, dl);
                }
            } else {
                #pragma unroll
                for (int v = 0; v < 8; v++) {
                    *reinterpret_cast<uint32_t*>(arow + (j0 + 4 * v) * 2)       = 0u;
                    *reinterpret_cast<uint32_t*>(arow + (j0 + 4 * v + 2) * 2)   = 0u;
                    *reinterpret_cast<uint32_t*>(arow + (64 + j0 + 4 * v) * 2)     = 0u;
                    *reinterpret_cast<uint32_t*>(arow + (64 + j0 + 4 * v + 2) * 2) = 0u;
                }
            }
        }
        __syncthreads();

        uint32_t af[8][4];
        #pragma unroll
        for (int kb = 0; kb < 8; kb++) ldsm4(af[kb], a_ld + kb * 32);

        const int gn0 = n0 + wid * 16 + rsub;
        const int gn1 = gn0 + 8;

        #pragma unroll
        for (int nb2 = 0; nb2 < 12; nb2++) {
            float acc[2][4];
            #pragma unroll
            for (int p = 0; p < 2; p++)
                #pragma unroll
                for (int q = 0; q < 4; q++) acc[p][q] = 0.f;
            uint32_t bf[4][4];
            #pragma unroll
            for (int kb = 0; kb < 4; kb++)
                ldsm4t(bf[kb], b_ld + nb2 * 32 + kb * (16 * QW_STRIDE));
            #pragma unroll
            for (int kc = 0; kc < 8; kc++) {
                mma16816(acc[0], af[kc], bf[kc & 3][0], bf[kc & 3][1]);
                mma16816(acc[1], af[kc], bf[kc & 3][2], bf[kc & 3][3]);
            }
            #pragma unroll
            for (int kb = 0; kb < 4; kb++)
                ldsm4t(bf[kb], b_ld + nb2 * 32 + (64 + kb * 16) * QW_STRIDE);
            #pragma unroll
            for (int kc = 0; kc < 4; kc++) {
                mma16816(acc[0], af[kc], bf[kc][0], bf[kc][1]);
                mma16816(acc[1], af[kc], bf[kc][2], bf[kc][3]);
            }
            const int c0 = nb2 * 16 + cpair;
            if (gn0 < N) {
                *reinterpret_cast<float2*>(g_Q + (size_t)gn0 * 192 + c0)     = make_float2(acc[0][0], acc[0][1]);
                *reinterpret_cast<float2*>(g_Q + (size_t)gn0 * 192 + c0 + 8) = make_float2(acc[1][0], acc[1][1]);
            }
            if (gn1 < N) {
                *reinterpret_cast<float2*>(g_Q + (size_t)gn1 * 192 + c0)     = make_float2(acc[0][2], acc[0][3]);
                *reinterpret_cast<float2*>(g_Q + (size_t)gn1 * 192 + c0 + 8) = make_float2(acc[1][2], acc[1][3]);
            }
        }
    }
}

// -------------------------------------------------------------- edge pipeline
// 128-edge tiles. Stage1 scalar f32x2 -> A [Ahi|Alo] bf16; stages 2&3 are
// split-bf16 mma.sync GEMMs (hi*hi + lo*hi via K=128 pass, hi*lo via K=64 pass).
#define A_STRIDE 272
#define W_STRIDE 144
#define SM_A     0                       // 128 * 272 = 34816
#define SM_W2    34816                   // [Bhi(64) ; Blo(64)] x 144B = 18432
#define SM_WC1   53248                   // 18432
#define SM_W1C   71680                   // fp32 16x64 = 4096
#define SM_MISC  75776                   // w1sq|b1e|b2e|bc1|wc2 = 5*256
#define SM_RIJ   77056                   // 128 * float4
#define SM_ROW   79104                   // 128 * int
#define SM_EDGE_BYTES 79616

__device__ __forceinline__ void gemm_split(uint32_t a_ld, uint32_t b_ld, float acc[8][4]) {
    uint32_t af[8][4];
    #pragma unroll
    for (int kb = 0; kb < 8; kb++) ldsm4(af[kb], a_ld + kb * 32);
    #pragma unroll
    for (int nb2 = 0; nb2 < 4; nb2++) {
        uint32_t bf[4][4];
        #pragma unroll
        for (int kb = 0; kb < 4; kb++)
            ldsm4t(bf[kb], b_ld + nb2 * 32 + kb * (16 * W_STRIDE));
        #pragma unroll
        for (int kc = 0; kc < 8; kc++) {
            mma16816(acc[2 * nb2],     af[kc], bf[kc & 3][0], bf[kc & 3][1]);
            mma16816(acc[2 * nb2 + 1], af[kc], bf[kc & 3][2], bf[kc & 3][3]);
        }
        #pragma unroll
        for (int kb = 0; kb < 4; kb++)
            ldsm4t(bf[kb], b_ld + nb2 * 32 + (64 + kb * 16) * W_STRIDE);
        #pragma unroll
        for (int kc = 0; kc < 4; kc++) {
            mma16816(acc[2 * nb2],     af[kc], bf[kc][0], bf[kc][1]);
            mma16816(acc[2 * nb2 + 1], af[kc], bf[kc][2], bf[kc][3]);
        }
    }
}

__global__ __launch_bounds__(256) void edge_kernel(
    const float* __restrict__ x, const float* __restrict__ edge_fea,
    const float* __restrict__ w1e, const float* __restrict__ b1e,
    const float* __restrict__ w2e, const float* __restrict__ b2e,
    const float* __restrict__ wc1, const float* __restrict__ bc1,
    const float* __restrict__ wc2, const float* __restrict__ bc2,
    const int* __restrict__ row, const int* __restrict__ col, int M)
{
    extern __shared__ __align__(1024) char smem[];
    const uint32_t sb = s2u(smem);
    const int tid = threadIdx.x;
    const int wid = tid >> 5, lane = tid & 31;

    float* w1sq_s = (float*)(smem + SM_MISC);
    float* b1e_s  = w1sq_s + 64;
    float* b2e_s  = b1e_s + 64;
    float* bc1_s  = b2e_s + 64;
    float* wc2_s  = bc1_s + 64;
    float4* rijs  = (float4*)(smem + SM_RIJ);
    int*   rowix  = (int*)(smem + SM_ROW);

    // ---- preload weights (packed u32 split stores)
    for (int i = tid; i < 1024; i += 256) ((float*)(smem + SM_W1C))[i] = w1e[129 * 64 + i];
    if (tid < 64) {
        w1sq_s[tid] = w1e[tid];
        b1e_s[tid] = b1e[tid];
        b2e_s[tid] = b2e[tid];
        bc1_s[tid] = bc1[tid];
        wc2_s[tid] = wc2[tid];
    }
    for (int i = tid; i < 2048; i += 256) {
        int k = i >> 5, np = i & 31;
        int n0b = np * 2;
        __nv_bfloat16 h0, l0, h1, l1;
        bf_split(w2e[k * 64 + n0b], h0, l0);
        bf_split(w2e[k * 64 + n0b + 1], h1, l1);
        *reinterpret_cast<uint32_t*>(smem + SM_W2 + k * W_STRIDE + n0b * 2) = pkbf(h0, h1);
        *reinterpret_cast<uint32_t*>(smem + SM_W2 + (64 + k) * W_STRIDE + n0b * 2) = pkbf(l0, l1);
        bf_split(wc1[k * 64 + n0b], h0, l0);
        bf_split(wc1[k * 64 + n0b + 1], h1, l1);
        *reinterpret_cast<uint32_t*>(smem + SM_WC1 + k * W_STRIDE + n0b * 2) = pkbf(h0, h1);
        *reinterpret_cast<uint32_t*>(smem + SM_WC1 + (64 + k) * W_STRIDE + n0b * 2) = pkbf(l0, l1);
    }
    const float bc2v = bc2[0];
    __syncthreads();

    // static per-thread ldmatrix addresses
    const uint32_t a_ld = sb + SM_A + (uint32_t)(wid * 16 + (lane & 15)) * A_STRIDE
                        + ((lane >> 4) << 4);
    const int g = lane >> 3, rr = lane & 7;
    const uint32_t b2_ld = sb + SM_W2  + (uint32_t)((g & 1) * 8 + rr) * W_STRIDE + (g >> 1) * 16;
    const uint32_t bc_ld = sb + SM_WC1 + (uint32_t)((g & 1) * 8 + rr) * W_STRIDE + (g >> 1) * 16;

    const int rsub = lane >> 2, cpair = (lane & 3) * 2;
    const int le0 = wid * 16 + rsub, le1 = le0 + 8;
    char* ar0 = smem + SM_A + le0 * A_STRIDE;
    char* ar1 = smem + SM_A + le1 * A_STRIDE;

    const int ntile = (M + 127) >> 7;

    for (int tile = blockIdx.x; tile < ntile; tile += gridDim.x) {
        const int e0 = tile << 7;
        // ================= stage 1: h1 = silu(L1) -> A [hi|lo]
        {
            const int le = tid >> 1, sub = tid & 1;
            const int m = e0 + le;
            const bool valid = (m < M);
            int r = 0, c = 0;
            float dx = 0.f, dy = 0.f, dz = 0.f;
            if (valid) {
                r = row[m]; c = col[m];
                dx = x[r * 3 + 0] - x[c * 3 + 0];
                dy = x[r * 3 + 1] - x[c * 3 + 1];
                dz = x[r * 3 + 2] - x[c * 3 + 2];
            }
            const float sq = dx * dx + dy * dy + dz * dz;
            if (sub == 0) {
                rijs[le] = make_float4(dx, dy, dz, sq);
                rowix[le] = valid ? r : -1;
            }
            const int j0 = sub << 5;
            u64t acc[16];
            {
                const ulonglong2* qr2 = reinterpret_cast<const ulonglong2*>(g_Q + (size_t)r * 192 + j0);
                const ulonglong2* qc2 = reinterpret_cast<const ulonglong2*>(g_Q + (size_t)c * 192 + 64 + j0);
                const u64t* ws2 = reinterpret_cast<const u64t*>(w1sq_s + j0);
                const u64t* bb2 = reinterpret_cast<const u64t*>(b1e_s + j0);
                const u64t sq2 = pk2(sq, sq);
                #pragma unroll
                for (int v = 0; v < 8; v++) {
                    ulonglong2 a = qr2[v], b = qc2[v];
                    acc[2 * v]     = fma2(sq2, ws2[2 * v],     add2(add2(a.x, b.x), bb2[2 * v]));
                    acc[2 * v + 1] = fma2(sq2, ws2[2 * v + 1], add2(add2(a.y, b.y), bb2[2 * v + 1]));
                }
            }
            const float4* efp = reinterpret_cast<const float4*>(edge_fea + (size_t)m * 16);
            const u64t* W1c2 = reinterpret_cast<const u64t*>(smem + SM_W1C);
            #pragma unroll
            for (int f4 = 0; f4 < 4; f4++) {
                float4 ef = valid ? efp[f4] : make_float4(0.f, 0.f, 0.f, 0.f);
                float efs[4] = {ef.x, ef.y, ef.z, ef.w};
                #pragma unroll
                for (int ff = 0; ff < 4; ff++) {
                    u64t e2 = pk2(efs[ff], efs[ff]);
                    const u64t* wr = W1c2 + (f4 * 4 + ff) * 32 + (j0 >> 1);
                    #pragma unroll
                    for (int j = 0; j < 16; j++) acc[j] = fma2(e2, wr[j], acc[j]);
                }
            }
            char* arow = smem + SM_A + le * A_STRIDE;
            #pragma unroll
            for (int j = 0; j < 16; j++) {
                float a, b; unpk2(acc[j], a, b);
                a = silu_t(a); b = silu_t(b);
                __nv_bfloat16 ah, al, bh, bl;
                bf_split(a, ah, al); bf_split(b, bh, bl);
                *reinterpret_cast<uint32_t*>(arow + (j0 + 2 * j) * 2) = pkbf(ah, bh);
                *reinterpret_cast<uint32_t*>(arow + (64 + j0 + 2 * j) * 2) = pkbf(al, bl);
            }
        }
        __syncthreads();

        // ================= GEMM1: D2 = h1 @ w2e  (split-bf16)
        float acc[8][4];
        #pragma unroll
        for (int nb = 0; nb < 8; nb++)
            #pragma unroll
            for (int q = 0; q < 4; q++) acc[nb][q] = 0.f;
        gemm_split(a_ld, b2_ld, acc);

        // ================= epilogue 2: msg = silu(D2+b2e); A<-msg hi/lo;
        // tot_msg atomics as red4 via pairwise lane exchange (halved op count)
        {
            const int rw0 = rowix[le0], rw1 = rowix[le1];
            const int par = lane & 1;
            #pragma unroll
            for (int nb = 0; nb < 8; nb++) {
                const int c = nb * 8 + cpair;
                float v00 = silu_t(acc[nb][0] + b2e_s[c]);
                float v01 = silu_t(acc[nb][1] + b2e_s[c + 1]);
                float v10 = silu_t(acc[nb][2] + b2e_s[c]);
                float v11 = silu_t(acc[nb][3] + b2e_s[c + 1]);
                __nv_bfloat16 h0, l0, h1b, l1;
                bf_split(v00, h0, l0); bf_split(v01, h1b, l1);
                *reinterpret_cast<uint32_t*>(ar0 + c * 2) = pkbf(h0, h1b);
                *reinterpret_cast<uint32_t*>(ar0 + (64 + c) * 2) = pkbf(l0, l1);
                bf_split(v10, h0, l0); bf_split(v11, h1b, l1);
                *reinterpret_cast<uint32_t*>(ar1 + c * 2) = pkbf(h0, h1b);
                *reinterpret_cast<uint32_t*>(ar1 + (64 + c) * 2) = pkbf(l0, l1);
                // exchange: even lane -> edge le0 (needs odd's v00,v01);
                //           odd lane  -> edge le1 (needs even's v10,v11)
                u64t send = par ? pk2(v00, v01) : pk2(v10, v11);
                u64t got = __shfl_xor_sync(0xffffffffu, send, 1);
                float g0, g1; unpk2(got, g0, g1);
                if (par) {
                    if (rw1 >= 0)
                        red4(g_totmsg + (size_t)rw1 * 64 + nb * 8 + (cpair - 2), g0, g1, v10, v11);
                } else {
                    if (rw0 >= 0)
                        red4(g_totmsg + (size_t)rw0 * 64 + nb * 8 + cpair, v00, v01, g0, g1);
                }
            }
        }
        __syncwarp();

        // ================= GEMM2: D3 = msg @ wc1  (split-bf16)
        #pragma unroll
        for (int nb = 0; nb < 8; nb++)
            #pragma unroll
            for (int q = 0; q < 4; q++) acc[nb][q] = 0.f;
        gemm_split(a_ld, bc_ld, acc);

        // ================= epilogue 3: cm = silu(D3+bc1).wc2 + bc2; totf atomics
        {
            float p0 = 0.f, p1 = 0.f;
            #pragma unroll
            for (int nb = 0; nb < 8; nb++) {
                const int c = nb * 8 + cpair;
                p0 += silu_t(acc[nb][0] + bc1_s[c]) * wc2_s[c]
                    + silu_t(acc[nb][1] + bc1_s[c + 1]) * wc2_s[c + 1];
                p1 += silu_t(acc[nb][2] + bc1_s[c]) * wc2_s[c]
                    + silu_t(acc[nb][3] + bc1_s[c + 1]) * wc2_s[c + 1];
            }
            p0 += __shfl_xor_sync(0xffffffffu, p0, 1);
            p0 += __shfl_xor_sync(0xffffffffu, p0, 2);
            p1 += __shfl_xor_sync(0xffffffffu, p1, 1);
            p1 += __shfl_xor_sync(0xffffffffu, p1, 2);
            if ((lane & 3) == 0) {
                int rw = rowix[le0];
                if (rw >= 0) {
                    float cm = p0 + bc2v;
                    float4 rrj = rijs[le0];
                    red4(g_totf + (size_t)rw * 4, rrj.x * cm, rrj.y * cm, rrj.z * cm, 1.0f);
                }
                rw = rowix[le1];
                if (rw >= 0) {
                    float cm = p1 + bc2v;
                    float4 rrj = rijs[le1];
                    red4(g_totf + (size_t)rw * 4, rrj.x * cm, rrj.y * cm, rrj.z * cm, 1.0f);
                }
            }
        }
        __syncthreads();
    }
}

// ------------------------------------------------------------- node finalize
#define NODE_SMEM_FLOATS (4096 + 4096 + 64 + 64 + 64 * 68 * 2)

__global__ __launch_bounds__(256) void node_kernel(
    const float* __restrict__ x,
    const float* __restrict__ wn1, const float* __restrict__ bn1,
    const float* __restrict__ wn2, const float* __restrict__ bn2,
    float* __restrict__ out, int N)
{
    extern __shared__ float sm[];
    float* Wb  = sm;
    float* W2  = Wb + 4096;
    float* b1s = W2 + 4096;
    float* b2s = b1s + 64;
    float* tmT = b2s + 64;
    float* uT  = tmT + 64 * 68;

    const int tid = threadIdx.x;
    for (int i = tid; i < 4096; i += 256) { Wb[i] = wn1[4096 + i]; W2[i] = wn2[i]; }
    if (tid < 64) { b1s[tid] = bn1[tid]; b2s[tid] = bn2[tid]; }
    __syncthreads();

    const int ty = tid >> 5, tx = tid & 31;
    const int r0 = ty << 3, c0 = tx << 1;
    float* out_h = out + (size_t)N * 3;
    const int ntile = (N + 63) >> 6;

    for (int tile = blockIdx.x; tile < ntile; tile += gridDim.x) {
        const int n0 = tile << 6;
        if (tid < 64) {
            int n = n0 + tid;
            if (n < N) {
                float4 tf = *reinterpret_cast<float4*>(g_totf + (size_t)n * 4);
                float dnm = fmaxf(tf.w, 1.0f);
                float fx = fminf(fmaxf(tf.x / dnm, -100.f), 100.f);
                float fy = fminf(fmaxf(tf.y / dnm, -100.f), 100.f);
                float fz = fminf(fmaxf(tf.z / dnm, -100.f), 100.f);
                out[n * 3 + 0] = x[n * 3 + 0] + fx;
                out[n * 3 + 1] = x[n * 3 + 1] + fy;
                out[n * 3 + 2] = x[n * 3 + 2] + fz;
            }
        }
        {
            const int i = tid >> 2, cs = (tid & 3) * 16;
            const int n = n0 + i;
            #pragma unroll
            for (int v = 0; v < 4; v++) {
                float4 t = (n < N)
                    ? *reinterpret_cast<const float4*>(g_totmsg + (size_t)n * 64 + cs + 4 * v)
                    : make_float4(0.f, 0.f, 0.f, 0.f);
                tmT[(cs + 4 * v + 0) * 68 + i] = t.x;
                tmT[(cs + 4 * v + 1) * 68 + i] = t.y;
                tmT[(cs + 4 * v + 2) * 68 + i] = t.z;
                tmT[(cs + 4 * v + 3) * 68 + i] = t.w;
            }
        }
        __syncthreads();
        u64t acc[4][2];
        {
            float q[8][2];
            #pragma unroll
            for (int e = 0; e < 8; e++) {
                int n = n0 + r0 + e;
                float2 qq = (n < N)
                    ? *reinterpret_cast<const float2*>(g_Q + (size_t)n * 192 + 128 + c0)
                    : make_float2(0.f, 0.f);
                q[e][0] = qq.x; q[e][1] = qq.y;
            }
            #pragma unroll
            for (int p = 0; p < 4; p++)
                #pragma unroll
                for (int c = 0; c < 2; c++)
                    acc[p][c] = pk2(q[2 * p][c] + b1s[c0 + c], q[2 * p + 1][c] + b1s[c0 + c]);
        }
        #pragma unroll 4
        for (int k = 0; k < 64; k++) {
            const ulonglong2* ar = reinterpret_cast<const ulonglong2*>(tmT + k * 68 + r0);
            ulonglong2 a01 = ar[0], a23 = ar[1];
            u64t a[4] = {a01.x, a01.y, a23.x, a23.y};
            float2 wv = *reinterpret_cast<const float2*>(Wb + k * 64 + c0);
            u64t b0 = pk2(wv.x, wv.x), b1 = pk2(wv.y, wv.y);
            #pragma unroll
            for (int p = 0; p < 4; p++) {
                acc[p][0] = fma2(a[p], b0, acc[p][0]);
                acc[p][1] = fma2(a[p], b1, acc[p][1]);
            }
        }
        __syncthreads();
        {
            u64t* uT64 = reinterpret_cast<u64t*>(uT);
            #pragma unroll
            for (int c = 0; c < 2; c++)
                #pragma unroll
                for (int p = 0; p < 4; p++) {
                    float a, b; unpk2(acc[p][c], a, b);
                    uT64[((c0 + c) * 68 + r0 + 2 * p) >> 1] = pk2(silu_f(a), silu_f(b));
                }
        }
        __syncthreads();
        u64t acc2[4][2];
        #pragma unroll
        for (int p = 0; p < 4; p++)
            #pragma unroll
            for (int c = 0; c < 2; c++)
                acc2[p][c] = pk2(b2s[c0 + c], b2s[c0 + c]);
        #pragma unroll 4
        for (int k = 0; k < 64; k++) {
            const ulonglong2* ar = reinterpret_cast<const ulonglong2*>(uT + k * 68 + r0);
            ulonglong2 a01 = ar[0], a23 = ar[1];
            u64t a[4] = {a01.x, a01.y, a23.x, a23.y};
            float2 wv = *reinterpret_cast<const float2*>(W2 + k * 64 + c0);
            u64t b0 = pk2(wv.x, wv.x), b1 = pk2(wv.y, wv.y);
            #pragma unroll
            for (int p = 0; p < 4; p++) {
                acc2[p][0] = fma2(a[p], b0, acc2[p][0]);
                acc2[p][1] = fma2(a[p], b1, acc2[p][1]);
            }
        }
        #pragma unroll
        for (int p = 0; p < 4; p++) {
            float o00, o10, o01, o11;
            unpk2(acc2[p][0], o00, o10);
            unpk2(acc2[p][1], o01, o11);
            int n = n0 + r0 + 2 * p;
            if (n < N)
                *reinterpret_cast<float2*>(out_h + (size_t)n * 64 + c0) = make_float2(o00, o01);
            if (n + 1 < N)
                *reinterpret_cast<float2*>(out_h + (size_t)(n + 1) * 64 + c0) = make_float2(o10, o11);
        }
        __syncthreads();
    }
}

// -------------------------------------------------------------------- launch
extern "C" void kernel_launch(void* const* d_in, const int* in_sizes, int n_in,
                              void* d_out, int out_size)
{
    const float* x        = (const float*)d_in[0];
    const float* h        = (const float*)d_in[1];
    const float* edge_fea = (const float*)d_in[2];
    const float* w1e      = (const float*)d_in[3];
    const float* b1e      = (const float*)d_in[4];
    const float* w2e      = (const float*)d_in[5];
    const float* b2e      = (const float*)d_in[6];
    const float* wc1      = (const float*)d_in[7];
    const float* bc1      = (const float*)d_in[8];
    const float* wc2      = (const float*)d_in[9];
    const float* bc2      = (const float*)d_in[10];
    const float* wn1      = (const float*)d_in[11];
    const float* bn1      = (const float*)d_in[12];
    const float* wn2      = (const float*)d_in[13];
    const float* bn2      = (const float*)d_in[14];
    const int*   row      = (const int*)d_in[15];
    const int*   col      = (const int*)d_in[16];
    float* out = (float*)d_out;

    const int N = in_sizes[1] / 64;
    const int M = in_sizes[15];

    const int node_smem = NODE_SMEM_FLOATS * 4;
    cudaFuncSetAttribute(precompQ, cudaFuncAttributeMaxDynamicSharedMemorySize, QSM_BYTES);
    cudaFuncSetAttribute(edge_kernel, cudaFuncAttributeMaxDynamicSharedMemorySize, SM_EDGE_BYTES);
    cudaFuncSetAttribute(node_kernel, cudaFuncAttributeMaxDynamicSharedMemorySize, node_smem);

    precompQ<<<304, 256, QSM_BYTES>>>(h, w1e, wn1, N);
    edge_kernel<<<304, 256, SM_EDGE_BYTES>>>(x, edge_fea, w1e, b1e, w2e, b2e,
                                             wc1, bc1, wc2, bc2, row, col, M);
    node_kernel<<<304, 256, node_smem>>>(x, wn1, bn1, wn2, bn2, out, N);
}

// round 16
// speedup vs baseline: 1.0594x; 1.0594x over previous
#include <cuda_runtime.h>
#include <cuda_bf16.h>
#include <cstdint>
#include <cstdio>

#define NMAX 50000

// scratch (allocation-free: __device__ globals)
__device__ __align__(16) float g_Q[NMAX * 192];      // [h@W1a | h@W1b | h@Wn1a]
__device__ __align__(16) float g_totf[NMAX * 4];     // {fx, fy, fz, deg}
__device__ __align__(16) float g_totmsg[NMAX * 64];

typedef unsigned long long u64t;

__device__ __forceinline__ float silu_f(float v) {
    return __fdividef(v, 1.0f + __expf(-v));
}
// 1-MUFU silu via tanh.approx: silu(x) = 0.5x*(1+tanh(0.5x))
__device__ __forceinline__ float silu_t(float v) {
    float hx = 0.5f * v, t;
    asm("tanh.approx.f32 %0,%1;" : "=f"(t) : "f"(hx));
    return fmaf(hx, t, hx);
}
__device__ __forceinline__ u64t pk2(float lo, float hi) {
    u64t r; asm("mov.b64 %0,{%1,%2};" : "=l"(r) : "f"(lo), "f"(hi)); return r;
}
__device__ __forceinline__ void unpk2(u64t v, float& a, float& b) {
    asm("mov.b64 {%0,%1},%2;" : "=f"(a), "=f"(b) : "l"(v));
}
__device__ __forceinline__ u64t fma2(u64t a, u64t b, u64t c) {
    u64t d; asm("fma.rn.f32x2 %0,%1,%2,%3;" : "=l"(d) : "l"(a), "l"(b), "l"(c)); return d;
}
__device__ __forceinline__ u64t add2(u64t a, u64t b) {
    u64t d; asm("add.rn.f32x2 %0,%1,%2;" : "=l"(d) : "l"(a), "l"(b)); return d;
}
__device__ __forceinline__ void red4(float* p, float a, float b, float c, float d) {
    asm volatile("red.global.add.v4.f32 [%0], {%1,%2,%3,%4};"
                 :: "l"(p), "f"(a), "f"(b), "f"(c), "f"(d) : "memory");
}
__device__ __forceinline__ void red2(float* p, float a, float b) {
    asm volatile("red.global.add.v2.f32 [%0], {%1,%2};"
                 :: "l"(p), "f"(a), "f"(b) : "memory");
}
__device__ __forceinline__ void bf_split(float v, __nv_bfloat16& h, __nv_bfloat16& l) {
    h = __float2bfloat16(v);
    l = __float2bfloat16(v - __bfloat162float(h));
}
__device__ __forceinline__ uint32_t pkbf(__nv_bfloat16 a, __nv_bfloat16 b) {
    __nv_bfloat162 t; t.x = a; t.y = b;
    return *reinterpret_cast<uint32_t*>(&t);
}
__device__ __forceinline__ uint32_t s2u(const void* p) {
    uint32_t a;
    asm("{ .reg .u64 t; cvta.to.shared.u64 t, %1; cvt.u32.u64 %0, t; }" : "=r"(a) : "l"(p));
    return a;
}
__device__ __forceinline__ void mma16816(float* d, const uint32_t* a, uint32_t b0, uint32_t b1) {
    asm volatile(
        "mma.sync.aligned.m16n8k16.row.col.f32.bf16.bf16.f32 "
        "{%0,%1,%2,%3},{%4,%5,%6,%7},{%8,%9},{%0,%1,%2,%3};"
        : "+f"(d[0]), "+f"(d[1]), "+f"(d[2]), "+f"(d[3])
        : "r"(a[0]), "r"(a[1]), "r"(a[2]), "r"(a[3]), "r"(b0), "r"(b1));
}
__device__ __forceinline__ void ldsm4(uint32_t* r, uint32_t addr) {
    asm volatile("ldmatrix.sync.aligned.m8n8.x4.shared.b16 {%0,%1,%2,%3},[%4];"
        : "=r"(r[0]), "=r"(r[1]), "=r"(r[2]), "=r"(r[3]) : "r"(addr));
}
__device__ __forceinline__ void ldsm4t(uint32_t* r, uint32_t addr) {
    asm volatile("ldmatrix.sync.aligned.m8n8.x4.trans.shared.b16 {%0,%1,%2,%3},[%4];"
        : "=r"(r[0]), "=r"(r[1]), "=r"(r[2]), "=r"(r[3]) : "r"(addr));
}

// ------------------------------------------------- per-node linear precompute
// g_Q[n][0:192] = h[n] @ [W1a | W1b | Wn1a], split-bf16 HMMA GEMM.
// All per-tile state is warp-stripe-local -> only __syncwarp in the loop.
#define QA_STRIDE 272
#define QW_STRIDE 400
#define QSM_A 0                 // 128 * 272 = 34816
#define QSM_W 34816             // 128 * 400 = 51200 ([Whi(64 k-rows); Wlo(64)] x 192 cols)
#define QSM_BYTES 86016

__global__ __launch_bounds__(256) void precompQ(
    const float* __restrict__ h, const float* __restrict__ w1e,
    const float* __restrict__ wn1, int N)
{
    extern __shared__ __align__(1024) char qsm[];
    const uint32_t sb = s2u(qsm);
    const int tid = threadIdx.x;
    const int wid = tid >> 5, lane = tid & 31;

    // zero accumulators (independent of the rest)
    {
        int gi = blockIdx.x * blockDim.x + tid;
        int gs = gridDim.x * blockDim.x;
        float4 z = make_float4(0.f, 0.f, 0.f, 0.f);
        float4* tf = reinterpret_cast<float4*>(g_totf);
        float4* tm = reinterpret_cast<float4*>(g_totmsg);
        for (int k = gi; k < N; k += gs) tf[k] = z;
        for (int k = gi; k < N * 16; k += gs) tm[k] = z;
    }

    // stage + split weights ONCE: k (0..63) x col-pair cp (0..95), packed u32 stores
    for (int i = tid; i < 64 * 96; i += 256) {
        int k = i / 96, cp = i - k * 96;
        int c0 = cp * 2, c1 = c0 + 1;
        float v0 = (c0 < 64) ? w1e[(1 + k) * 64 + c0]
                 : (c0 < 128) ? w1e[(65 + k) * 64 + (c0 - 64)]
                              : wn1[k * 64 + (c0 - 128)];
        float v1 = (c1 < 64) ? w1e[(1 + k) * 64 + c1]
                 : (c1 < 128) ? w1e[(65 + k) * 64 + (c1 - 64)]
                              : wn1[k * 64 + (c1 - 128)];
        __nv_bfloat16 h0, l0, h1, l1;
        bf_split(v0, h0, l0); bf_split(v1, h1, l1);
        *reinterpret_cast<uint32_t*>(qsm + QSM_W + k * QW_STRIDE + c0 * 2) = pkbf(h0, h1);
        *reinterpret_cast<uint32_t*>(qsm + QSM_W + (64 + k) * QW_STRIDE + c0 * 2) = pkbf(l0, l1);
    }
    __syncthreads();   // weights visible to all warps before any GEMM

    // static per-thread ldmatrix addresses
    const uint32_t a_ld = sb + QSM_A + (uint32_t)(wid * 16 + (lane & 15)) * QA_STRIDE
                        + ((lane >> 4) << 4);
    const int g = lane >> 3, rr = lane & 7;
    const uint32_t b_ld = sb + QSM_W + (uint32_t)((g & 1) * 8 + rr) * QW_STRIDE + (g >> 1) * 16;
    const int rsub = lane >> 2, cpair = (lane & 3) * 2;

    const int ntile = (N + 127) >> 7;
    for (int tile = blockIdx.x; tile < ntile; tile += gridDim.x) {
        const int n0 = tile << 7;
        __syncwarp();   // own-stripe ldsm reads of previous tile done before rewrite
        // stage h tile (warp-own 16-row stripe) -> A [hi|lo] bf16
        {
            const int le = tid >> 1, sub = tid & 1, j0 = sub << 5;
            const int n = n0 + le;
            char* arow = qsm + QSM_A + le * QA_STRIDE;
            if (n < N) {
                const float4* hp = reinterpret_cast<const float4*>(h + (size_t)n * 64 + j0);
                #pragma unroll
                for (int v = 0; v < 8; v++) {
                    float4 hv = hp[v];
                    __nv_bfloat16 ah, al, bh, bl, ch, cl, dh, dl;
                    bf_split(hv.x, ah, al); bf_split(hv.y, bh, bl);
                    bf_split(hv.z, ch, cl); bf_split(hv.w, dh, dl);
                    *reinterpret_cast<uint32_t*>(arow + (j0 + 4 * v) * 2)       = pkbf(ah, bh);
                    *reinterpret_cast<uint32_t*>(arow + (j0 + 4 * v + 2) * 2)   = pkbf(ch, dh);
                    *reinterpret_cast<uint32_t*>(arow + (64 + j0 + 4 * v) * 2)     = pkbf(al, bl);
                    *reinterpret_cast<uint32_t*>(arow + (64 + j0 + 4 * v + 2) * 2) = pkbf(cl, dl);
                }
            } else {
                #pragma unroll
                for (int v = 0; v < 8; v++) {
                    *reinterpret_cast<uint32_t*>(arow + (j0 + 4 * v) * 2)       = 0u;
                    *reinterpret_cast<uint32_t*>(arow + (j0 + 4 * v + 2) * 2)   = 0u;
                    *reinterpret_cast<uint32_t*>(arow + (64 + j0 + 4 * v) * 2)     = 0u;
                    *reinterpret_cast<uint32_t*>(arow + (64 + j0 + 4 * v + 2) * 2) = 0u;
                }
            }
        }
        __syncwarp();

        uint32_t af[8][4];
        #pragma unroll
        for (int kb = 0; kb < 8; kb++) ldsm4(af[kb], a_ld + kb * 32);

        const int gn0 = n0 + wid * 16 + rsub;
        const int gn1 = gn0 + 8;

        #pragma unroll
        for (int nb2 = 0; nb2 < 12; nb2++) {
            float acc[2][4];
            #pragma unroll
            for (int p = 0; p < 2; p++)
                #pragma unroll
                for (int q = 0; q < 4; q++) acc[p][q] = 0.f;
            uint32_t bf[4][4];
            #pragma unroll
            for (int kb = 0; kb < 4; kb++)
                ldsm4t(bf[kb], b_ld + nb2 * 32 + kb * (16 * QW_STRIDE));
            #pragma unroll
            for (int kc = 0; kc < 8; kc++) {
                mma16816(acc[0], af[kc], bf[kc & 3][0], bf[kc & 3][1]);
                mma16816(acc[1], af[kc], bf[kc & 3][2], bf[kc & 3][3]);
            }
            #pragma unroll
            for (int kb = 0; kb < 4; kb++)
                ldsm4t(bf[kb], b_ld + nb2 * 32 + (64 + kb * 16) * QW_STRIDE);
            #pragma unroll
            for (int kc = 0; kc < 4; kc++) {
                mma16816(acc[0], af[kc], bf[kc][0], bf[kc][1]);
                mma16816(acc[1], af[kc], bf[kc][2], bf[kc][3]);
            }
            const int c0 = nb2 * 16 + cpair;
            if (gn0 < N) {
                *reinterpret_cast<float2*>(g_Q + (size_t)gn0 * 192 + c0)     = make_float2(acc[0][0], acc[0][1]);
                *reinterpret_cast<float2*>(g_Q + (size_t)gn0 * 192 + c0 + 8) = make_float2(acc[1][0], acc[1][1]);
            }
            if (gn1 < N) {
                *reinterpret_cast<float2*>(g_Q + (size_t)gn1 * 192 + c0)     = make_float2(acc[0][2], acc[0][3]);
                *reinterpret_cast<float2*>(g_Q + (size_t)gn1 * 192 + c0 + 8) = make_float2(acc[1][2], acc[1][3]);
            }
        }
    }
}

// -------------------------------------------------------------- edge pipeline
// 128-edge tiles; ALL per-tile state is warp-stripe-local, so the tile loop
// uses only __syncwarp — the 8 warps run fully decoupled after the preamble.
#define A_STRIDE 272
#define W_STRIDE 144
#define SM_A     0                       // 128 * 272 = 34816
#define SM_W2    34816                   // [Bhi(64) ; Blo(64)] x 144B = 18432
#define SM_WC1   53248                   // 18432
#define SM_W1C   71680                   // fp32 16x64 = 4096
#define SM_MISC  75776                   // w1sq|b1e|b2e|bc1|wc2 = 5*256
#define SM_RIJ   77056                   // 128 * float4
#define SM_ROW   79104                   // 128 * int
#define SM_EDGE_BYTES 79616

__device__ __forceinline__ void gemm_split(uint32_t a_ld, uint32_t b_ld, float acc[8][4]) {
    uint32_t af[8][4];
    #pragma unroll
    for (int kb = 0; kb < 8; kb++) ldsm4(af[kb], a_ld + kb * 32);
    #pragma unroll
    for (int nb2 = 0; nb2 < 4; nb2++) {
        uint32_t bf[4][4];
        #pragma unroll
        for (int kb = 0; kb < 4; kb++)
            ldsm4t(bf[kb], b_ld + nb2 * 32 + kb * (16 * W_STRIDE));
        #pragma unroll
        for (int kc = 0; kc < 8; kc++) {
            mma16816(acc[2 * nb2],     af[kc], bf[kc & 3][0], bf[kc & 3][1]);
            mma16816(acc[2 * nb2 + 1], af[kc], bf[kc & 3][2], bf[kc & 3][3]);
        }
        #pragma unroll
        for (int kb = 0; kb < 4; kb++)
            ldsm4t(bf[kb], b_ld + nb2 * 32 + (64 + kb * 16) * W_STRIDE);
        #pragma unroll
        for (int kc = 0; kc < 4; kc++) {
            mma16816(acc[2 * nb2],     af[kc], bf[kc][0], bf[kc][1]);
            mma16816(acc[2 * nb2 + 1], af[kc], bf[kc][2], bf[kc][3]);
        }
    }
}

__global__ __launch_bounds__(256) void edge_kernel(
    const float* __restrict__ x, const float* __restrict__ edge_fea,
    const float* __restrict__ w1e, const float* __restrict__ b1e,
    const float* __restrict__ w2e, const float* __restrict__ b2e,
    const float* __restrict__ wc1, const float* __restrict__ bc1,
    const float* __restrict__ wc2, const float* __restrict__ bc2,
    const int* __restrict__ row, const int* __restrict__ col, int M)
{
    extern __shared__ __align__(1024) char smem[];
    const uint32_t sb = s2u(smem);
    const int tid = threadIdx.x;
    const int wid = tid >> 5, lane = tid & 31;

    float* w1sq_s = (float*)(smem + SM_MISC);
    float* b1e_s  = w1sq_s + 64;
    float* b2e_s  = b1e_s + 64;
    float* bc1_s  = b2e_s + 64;
    float* wc2_s  = bc1_s + 64;
    float4* rijs  = (float4*)(smem + SM_RIJ);
    int*   rowix  = (int*)(smem + SM_ROW);

    // ---- preload weights (packed u32 split stores)
    for (int i = tid; i < 1024; i += 256) ((float*)(smem + SM_W1C))[i] = w1e[129 * 64 + i];
    if (tid < 64) {
        w1sq_s[tid] = w1e[tid];
        b1e_s[tid] = b1e[tid];
        b2e_s[tid] = b2e[tid];
        bc1_s[tid] = bc1[tid];
        wc2_s[tid] = wc2[tid];
    }
    for (int i = tid; i < 2048; i += 256) {
        int k = i >> 5, np = i & 31;
        int n0b = np * 2;
        __nv_bfloat16 h0, l0, h1, l1;
        bf_split(w2e[k * 64 + n0b], h0, l0);
        bf_split(w2e[k * 64 + n0b + 1], h1, l1);
        *reinterpret_cast<uint32_t*>(smem + SM_W2 + k * W_STRIDE + n0b * 2) = pkbf(h0, h1);
        *reinterpret_cast<uint32_t*>(smem + SM_W2 + (64 + k) * W_STRIDE + n0b * 2) = pkbf(l0, l1);
        bf_split(wc1[k * 64 + n0b], h0, l0);
        bf_split(wc1[k * 64 + n0b + 1], h1, l1);
        *reinterpret_cast<uint32_t*>(smem + SM_WC1 + k * W_STRIDE + n0b * 2) = pkbf(h0, h1);
        *reinterpret_cast<uint32_t*>(smem + SM_WC1 + (64 + k) * W_STRIDE + n0b * 2) = pkbf(l0, l1);
    }
    const float bc2v = bc2[0];
    __syncthreads();   // weights visible to all warps; after this, warps decouple

    // static per-thread ldmatrix addresses
    const uint32_t a_ld = sb + SM_A + (uint32_t)(wid * 16 + (lane & 15)) * A_STRIDE
                        + ((lane >> 4) << 4);
    const int g = lane >> 3, rr = lane & 7;
    const uint32_t b2_ld = sb + SM_W2  + (uint32_t)((g & 1) * 8 + rr) * W_STRIDE + (g >> 1) * 16;
    const uint32_t bc_ld = sb + SM_WC1 + (uint32_t)((g & 1) * 8 + rr) * W_STRIDE + (g >> 1) * 16;

    const int rsub = lane >> 2, cpair = (lane & 3) * 2;
    const int le0 = wid * 16 + rsub, le1 = le0 + 8;
    char* ar0 = smem + SM_A + le0 * A_STRIDE;
    char* ar1 = smem + SM_A + le1 * A_STRIDE;

    const int ntile = (M + 127) >> 7;

    for (int tile = blockIdx.x; tile < ntile; tile += gridDim.x) {
        const int e0 = tile << 7;
        // ================= stage 1: h1 = silu(L1) -> A [hi|lo] (own stripe)
        {
            const int le = tid >> 1, sub = tid & 1;
            const int m = e0 + le;
            const bool valid = (m < M);
            int r = 0, c = 0;
            float dx = 0.f, dy = 0.f, dz = 0.f;
            if (valid) {
                r = row[m]; c = col[m];
                dx = x[r * 3 + 0] - x[c * 3 + 0];
                dy = x[r * 3 + 1] - x[c * 3 + 1];
                dz = x[r * 3 + 2] - x[c * 3 + 2];
            }
            const float sq = dx * dx + dy * dy + dz * dz;
            if (sub == 0) {
                rijs[le] = make_float4(dx, dy, dz, sq);
                rowix[le] = valid ? r : -1;
            }
            const int j0 = sub << 5;
            u64t acc[16];
            {
                const ulonglong2* qr2 = reinterpret_cast<const ulonglong2*>(g_Q + (size_t)r * 192 + j0);
                const ulonglong2* qc2 = reinterpret_cast<const ulonglong2*>(g_Q + (size_t)c * 192 + 64 + j0);
                const u64t* ws2 = reinterpret_cast<const u64t*>(w1sq_s + j0);
                const u64t* bb2 = reinterpret_cast<const u64t*>(b1e_s + j0);
                const u64t sq2 = pk2(sq, sq);
                #pragma unroll
                for (int v = 0; v < 8; v++) {
                    ulonglong2 a = qr2[v], b = qc2[v];
                    acc[2 * v]     = fma2(sq2, ws2[2 * v],     add2(add2(a.x, b.x), bb2[2 * v]));
                    acc[2 * v + 1] = fma2(sq2, ws2[2 * v + 1], add2(add2(a.y, b.y), bb2[2 * v + 1]));
                }
            }
            const float4* efp = reinterpret_cast<const float4*>(edge_fea + (size_t)m * 16);
            const u64t* W1c2 = reinterpret_cast<const u64t*>(smem + SM_W1C);
            #pragma unroll
            for (int f4 = 0; f4 < 4; f4++) {
                float4 ef = valid ? efp[f4] : make_float4(0.f, 0.f, 0.f, 0.f);
                float efs[4] = {ef.x, ef.y, ef.z, ef.w};
                #pragma unroll
                for (int ff = 0; ff < 4; ff++) {
                    u64t e2 = pk2(efs[ff], efs[ff]);
                    const u64t* wr = W1c2 + (f4 * 4 + ff) * 32 + (j0 >> 1);
                    #pragma unroll
                    for (int j = 0; j < 16; j++) acc[j] = fma2(e2, wr[j], acc[j]);
                }
            }
            char* arow = smem + SM_A + le * A_STRIDE;
            #pragma unroll
            for (int j = 0; j < 16; j++) {
                float a, b; unpk2(acc[j], a, b);
                a = silu_t(a); b = silu_t(b);
                __nv_bfloat16 ah, al, bh, bl;
                bf_split(a, ah, al); bf_split(b, bh, bl);
                *reinterpret_cast<uint32_t*>(arow + (j0 + 2 * j) * 2) = pkbf(ah, bh);
                *reinterpret_cast<uint32_t*>(arow + (64 + j0 + 2 * j) * 2) = pkbf(al, bl);
            }
        }
        __syncwarp();

        // ================= GEMM1: D2 = h1 @ w2e  (split-bf16)
        float acc[8][4];
        #pragma unroll
        for (int nb = 0; nb < 8; nb++)
            #pragma unroll
            for (int q = 0; q < 4; q++) acc[nb][q] = 0.f;
        gemm_split(a_ld, b2_ld, acc);

        // ================= epilogue 2: msg = silu(D2+b2e); A<-msg hi/lo; atomics
        {
            const int rw0 = rowix[le0], rw1 = rowix[le1];
            #pragma unroll
            for (int nb = 0; nb < 8; nb++) {
                const int c = nb * 8 + cpair;
                float v00 = silu_t(acc[nb][0] + b2e_s[c]);
                float v01 = silu_t(acc[nb][1] + b2e_s[c + 1]);
                float v10 = silu_t(acc[nb][2] + b2e_s[c]);
                float v11 = silu_t(acc[nb][3] + b2e_s[c + 1]);
                __nv_bfloat16 h0, l0, h1b, l1;
                bf_split(v00, h0, l0); bf_split(v01, h1b, l1);
                *reinterpret_cast<uint32_t*>(ar0 + c * 2) = pkbf(h0, h1b);
                *reinterpret_cast<uint32_t*>(ar0 + (64 + c) * 2) = pkbf(l0, l1);
                bf_split(v10, h0, l0); bf_split(v11, h1b, l1);
                *reinterpret_cast<uint32_t*>(ar1 + c * 2) = pkbf(h0, h1b);
                *reinterpret_cast<uint32_t*>(ar1 + (64 + c) * 2) = pkbf(l0, l1);
                if (rw0 >= 0) red2(g_totmsg + (size_t)rw0 * 64 + c, v00, v01);
                if (rw1 >= 0) red2(g_totmsg + (size_t)rw1 * 64 + c, v10, v11);
            }
        }
        __syncwarp();

        // ================= GEMM2: D3 = msg @ wc1  (split-bf16)
        #pragma unroll
        for (int nb = 0; nb < 8; nb++)
            #pragma unroll
            for (int q = 0; q < 4; q++) acc[nb][q] = 0.f;
        gemm_split(a_ld, bc_ld, acc);

        // ================= epilogue 3: cm = silu(D3+bc1).wc2 + bc2; totf atomics
        {
            float p0 = 0.f, p1 = 0.f;
            #pragma unroll
            for (int nb = 0; nb < 8; nb++) {
                const int c = nb * 8 + cpair;
                p0 += silu_t(acc[nb][0] + bc1_s[c]) * wc2_s[c]
                    + silu_t(acc[nb][1] + bc1_s[c + 1]) * wc2_s[c + 1];
                p1 += silu_t(acc[nb][2] + bc1_s[c]) * wc2_s[c]
                    + silu_t(acc[nb][3] + bc1_s[c + 1]) * wc2_s[c + 1];
            }
            p0 += __shfl_xor_sync(0xffffffffu, p0, 1);
            p0 += __shfl_xor_sync(0xffffffffu, p0, 2);
            p1 += __shfl_xor_sync(0xffffffffu, p1, 1);
            p1 += __shfl_xor_sync(0xffffffffu, p1, 2);
            if ((lane & 3) == 0) {
                int rw = rowix[le0];
                if (rw >= 0) {
                    float cm = p0 + bc2v;
                    float4 rrj = rijs[le0];
                    red4(g_totf + (size_t)rw * 4, rrj.x * cm, rrj.y * cm, rrj.z * cm, 1.0f);
                }
                rw = rowix[le1];
                if (rw >= 0) {
                    float cm = p1 + bc2v;
                    float4 rrj = rijs[le1];
                    red4(g_totf + (size_t)rw * 4, rrj.x * cm, rrj.y * cm, rrj.z * cm, 1.0f);
                }
            }
        }
        __syncwarp();
    }
}

// ------------------------------------------------------------- node finalize
#define NODE_SMEM_FLOATS (4096 + 4096 + 64 + 64 + 64 * 68 * 2)

__global__ __launch_bounds__(256) void node_kernel(
    const float* __restrict__ x,
    const float* __restrict__ wn1, const float* __restrict__ bn1,
    const float* __restrict__ wn2, const float* __restrict__ bn2,
    float* __restrict__ out, int N)
{
    extern __shared__ float sm[];
    float* Wb  = sm;
    float* W2  = Wb + 4096;
    float* b1s = W2 + 4096;
    float* b2s = b1s + 64;
    float* tmT = b2s + 64;
    float* uT  = tmT + 64 * 68;

    const int tid = threadIdx.x;
    for (int i = tid; i < 4096; i += 256) { Wb[i] = wn1[4096 + i]; W2[i] = wn2[i]; }
    if (tid < 64) { b1s[tid] = bn1[tid]; b2s[tid] = bn2[tid]; }
    __syncthreads();

    const int ty = tid >> 5, tx = tid & 31;
    const int r0 = ty << 3, c0 = tx << 1;
    float* out_h = out + (size_t)N * 3;
    const int ntile = (N + 63) >> 6;

    for (int tile = blockIdx.x; tile < ntile; tile += gridDim.x) {
        const int n0 = tile << 6;
        if (tid < 64) {
            int n = n0 + tid;
            if (n < N) {
                float4 tf = *reinterpret_cast<float4*>(g_totf + (size_t)n * 4);
                float dnm = fmaxf(tf.w, 1.0f);
                float fx = fminf(fmaxf(tf.x / dnm, -100.f), 100.f);
                float fy = fminf(fmaxf(tf.y / dnm, -100.f), 100.f);
                float fz = fminf(fmaxf(tf.z / dnm, -100.f), 100.f);
                out[n * 3 + 0] = x[n * 3 + 0] + fx;
                out[n * 3 + 1] = x[n * 3 + 1] + fy;
                out[n * 3 + 2] = x[n * 3 + 2] + fz;
            }
        }
        {
            const int i = tid >> 2, cs = (tid & 3) * 16;
            const int n = n0 + i;
            #pragma unroll
            for (int v = 0; v < 4; v++) {
                float4 t = (n < N)
                    ? *reinterpret_cast<const float4*>(g_totmsg + (size_t)n * 64 + cs + 4 * v)
                    : make_float4(0.f, 0.f, 0.f, 0.f);
                tmT[(cs + 4 * v + 0) * 68 + i] = t.x;
                tmT[(cs + 4 * v + 1) * 68 + i] = t.y;
                tmT[(cs + 4 * v + 2) * 68 + i] = t.z;
                tmT[(cs + 4 * v + 3) * 68 + i] = t.w;
            }
        }
        __syncthreads();
        u64t acc[4][2];
        {
            float q[8][2];
            #pragma unroll
            for (int e = 0; e < 8; e++) {
                int n = n0 + r0 + e;
                float2 qq = (n < N)
                    ? *reinterpret_cast<const float2*>(g_Q + (size_t)n * 192 + 128 + c0)
                    : make_float2(0.f, 0.f);
                q[e][0] = qq.x; q[e][1] = qq.y;
            }
            #pragma unroll
            for (int p = 0; p < 4; p++)
                #pragma unroll
                for (int c = 0; c < 2; c++)
                    acc[p][c] = pk2(q[2 * p][c] + b1s[c0 + c], q[2 * p + 1][c] + b1s[c0 + c]);
        }
        #pragma unroll 4
        for (int k = 0; k < 64; k++) {
            const ulonglong2* ar = reinterpret_cast<const ulonglong2*>(tmT + k * 68 + r0);
            ulonglong2 a01 = ar[0], a23 = ar[1];
            u64t a[4] = {a01.x, a01.y, a23.x, a23.y};
            float2 wv = *reinterpret_cast<const float2*>(Wb + k * 64 + c0);
            u64t b0 = pk2(wv.x, wv.x), b1 = pk2(wv.y, wv.y);
            #pragma unroll
            for (int p = 0; p < 4; p++) {
                acc[p][0] = fma2(a[p], b0, acc[p][0]);
                acc[p][1] = fma2(a[p], b1, acc[p][1]);
            }
        }
        __syncthreads();
        {
            u64t* uT64 = reinterpret_cast<u64t*>(uT);
            #pragma unroll
            for (int c = 0; c < 2; c++)
                #pragma unroll
                for (int p = 0; p < 4; p++) {
                    float a, b; unpk2(acc[p][c], a, b);
                    uT64[((c0 + c) * 68 + r0 + 2 * p) >> 1] = pk2(silu_f(a), silu_f(b));
                }
        }
        __syncthreads();
        u64t acc2[4][2];
        #pragma unroll
        for (int p = 0; p < 4; p++)
            #pragma unroll
            for (int c = 0; c < 2; c++)
                acc2[p][c] = pk2(b2s[c0 + c], b2s[c0 + c]);
        #pragma unroll 4
        for (int k = 0; k < 64; k++) {
            const ulonglong2* ar = reinterpret_cast<const ulonglong2*>(uT + k * 68 + r0);
            ulonglong2 a01 = ar[0], a23 = ar[1];
            u64t a[4] = {a01.x, a01.y, a23.x, a23.y};
            float2 wv = *reinterpret_cast<const float2*>(W2 + k * 64 + c0);
            u64t b0 = pk2(wv.x, wv.x), b1 = pk2(wv.y, wv.y);
            #pragma unroll
            for (int p = 0; p < 4; p++) {
                acc2[p][0] = fma2(a[p], b0, acc2[p][0]);
                acc2[p][1] = fma2(a[p], b1, acc2[p][1]);
            }
        }
        #pragma unroll
        for (int p = 0; p < 4; p++) {
            float o00, o10, o01, o11;
            unpk2(acc2[p][0], o00, o10);
            unpk2(acc2[p][1], o01, o11);
            int n = n0 + r0 + 2 * p;
            if (n < N)
                *reinterpret_cast<float2*>(out_h + (size_t)n * 64 + c0) = make_float2(o00, o01);
            if (n + 1 < N)
                *reinterpret_cast<float2*>(out_h + (size_t)(n + 1) * 64 + c0) = make_float2(o10, o11);
        }
        __syncthreads();
    }
}

// -------------------------------------------------------------------- launch
extern "C" void kernel_launch(void* const* d_in, const int* in_sizes, int n_in,
                              void* d_out, int out_size)
{
    const float* x        = (const float*)d_in[0];
    const float* h        = (const float*)d_in[1];
    const float* edge_fea = (const float*)d_in[2];
    const float* w1e      = (const float*)d_in[3];
    const float* b1e      = (const float*)d_in[4];
    const float* w2e      = (const float*)d_in[5];
    const float* b2e      = (const float*)d_in[6];
    const float* wc1      = (const float*)d_in[7];
    const float* bc1      = (const float*)d_in[8];
    const float* wc2      = (const float*)d_in[9];
    const float* bc2      = (const float*)d_in[10];
    const float* wn1      = (const float*)d_in[11];
    const float* bn1      = (const float*)d_in[12];
    const float* wn2      = (const float*)d_in[13];
    const float* bn2      = (const float*)d_in[14];
    const int*   row      = (const int*)d_in[15];
    const int*   col      = (const int*)d_in[16];
    float* out = (float*)d_out;

    const int N = in_sizes[1] / 64;
    const int M = in_sizes[15];

    const int node_smem = NODE_SMEM_FLOATS * 4;
    cudaFuncSetAttribute(precompQ, cudaFuncAttributeMaxDynamicSharedMemorySize, QSM_BYTES);
    cudaFuncSetAttribute(edge_kernel, cudaFuncAttributeMaxDynamicSharedMemorySize, SM_EDGE_BYTES);
    cudaFuncSetAttribute(node_kernel, cudaFuncAttributeMaxDynamicSharedMemorySize, node_smem);

    precompQ<<<304, 256, QSM_BYTES>>>(h, w1e, wn1, N);
    edge_kernel<<<304, 256, SM_EDGE_BYTES>>>(x, edge_fea, w1e, b1e, w2e, b2e,
                                             wc1, bc1, wc2, bc2, row, col, M);
    node_kernel<<<304, 256, node_smem>>>(x, wn1, bn1, wn2, bn2, out, N);
}